// round 1
// baseline (speedup 1.0000x reference)
#include <cuda_runtime.h>
#include <math.h>

// Problem constants
#define TT     2048
#define EE     768
#define HH     512          // H2
#define GATES  2048         // 4*H2
#define KK     7
#define START_TAG 5
#define STOP_TAG  6
#define NEGV  -10000.0f
#define NBLK   64           // CTAs per direction in the recurrence

// ---------------- scratch (device globals; no runtime allocation) ----------
__device__ float g_pre[2][TT][GATES];     // 32 MB: gate pre-activations (both dirs)
__device__ float g_hs[TT][2 * HH];        // 8 MB: [t][0:512]=fwd h, [512:1024]=bwd h
__device__ float g_feats[TT][KK];
__device__ float g_h[2][2][HH];           // double-buffered h broadcast [parity][dir][k]
__device__ int   g_cnt[64];               // barrier counters at [0] and [32] (pad lines)

// ---------------------------------------------------------------------------
// Kernel 0: init — reset barrier counters, seed h_buf parity 0 with h0
// ---------------------------------------------------------------------------
__global__ void init_kernel(const float* __restrict__ h0) {
    int tid = threadIdx.x;
    if (tid < 2) g_cnt[tid * 32] = 0;
    if (tid < 2 * HH) g_h[0][tid >> 9][tid & (HH - 1)] = h0[tid];
}

// ---------------------------------------------------------------------------
// Kernel 1: pre = embeds(@dir) @ W_ih^T + (b_ih + b_hh)
// Tiled fp32 GEMM. C[M=2048][N=2048], K=768. grid (32,32,2), 256 threads.
// For dir=1 the A rows are read reversed (xs = embeds[::-1]).
// ---------------------------------------------------------------------------
#define BM 64
#define BN 64
#define BK 16
__global__ void gemm_pre(const float* __restrict__ embeds,
                         const float* __restrict__ Wihf,
                         const float* __restrict__ Wihb,
                         const float* __restrict__ bihf, const float* __restrict__ bhhf,
                         const float* __restrict__ bihb, const float* __restrict__ bhhb) {
    const int dir = blockIdx.z;
    const float* __restrict__ Wih = dir ? Wihb : Wihf;
    const float* __restrict__ bi  = dir ? bihb : bihf;
    const float* __restrict__ bh  = dir ? bhhb : bhhf;

    __shared__ __align__(16) float As[BK][BM];
    __shared__ __align__(16) float Bs[BK][BN];

    const int tid = threadIdx.x;
    const int m0 = blockIdx.y * BM;
    const int n0 = blockIdx.x * BN;
    const int lm = tid & 63;          // 0..63
    const int lk = tid >> 6;          // 0..3 -> 4 k-values each (float4)
    const int tm = (tid >> 4) << 2;   // 0,4,...,60
    const int tn = (tid & 15) << 2;

    float acc[4][4] = {};

    const int arow = m0 + lm;
    const int grow = dir ? (TT - 1 - arow) : arow;
    const float* arow_p = embeds + (long)grow * EE;
    const float* brow_p = Wih + (long)(n0 + lm) * EE;

    for (int kk = 0; kk < EE; kk += BK) {
        float4 av = *(const float4*)(arow_p + kk + lk * 4);
        float4 bv = *(const float4*)(brow_p + kk + lk * 4);
        As[lk * 4 + 0][lm] = av.x; As[lk * 4 + 1][lm] = av.y;
        As[lk * 4 + 2][lm] = av.z; As[lk * 4 + 3][lm] = av.w;
        Bs[lk * 4 + 0][lm] = bv.x; Bs[lk * 4 + 1][lm] = bv.y;
        Bs[lk * 4 + 2][lm] = bv.z; Bs[lk * 4 + 3][lm] = bv.w;
        __syncthreads();
#pragma unroll
        for (int k = 0; k < BK; k++) {
            float4 a = *(const float4*)&As[k][tm];
            float4 b = *(const float4*)&Bs[k][tn];
            float ar[4] = {a.x, a.y, a.z, a.w};
            float br[4] = {b.x, b.y, b.z, b.w};
#pragma unroll
            for (int i = 0; i < 4; i++)
#pragma unroll
                for (int j = 0; j < 4; j++)
                    acc[i][j] += ar[i] * br[j];
        }
        __syncthreads();
    }

    float bias[4];
#pragma unroll
    for (int j = 0; j < 4; j++) bias[j] = bi[n0 + tn + j] + bh[n0 + tn + j];
#pragma unroll
    for (int i = 0; i < 4; i++) {
        int row = m0 + tm + i;
        float4 v;
        v.x = acc[i][0] + bias[0];
        v.y = acc[i][1] + bias[1];
        v.z = acc[i][2] + bias[2];
        v.w = acc[i][3] + bias[3];
        *(float4*)&g_pre[dir][row][n0 + tn] = v;
    }
}

// ---------------------------------------------------------------------------
// Kernel 2: persistent BiLSTM recurrence.
// grid (64, 2): 64 CTAs per direction, 8 hidden units per CTA (1 warp/unit).
// W_hh slice (8 units x 4 gates x 512) lives in dynamic SMEM (64 KB).
// Per step: acquire-spin on counter, load h into SMEM, 4 dots/warp, warp
// reduce, gate math on lane 0, publish h, fence, arrive.
// ---------------------------------------------------------------------------
__global__ void lstm_rec(const float* __restrict__ c0,
                         const float* __restrict__ Whhf,
                         const float* __restrict__ Whhb) {
    extern __shared__ __align__(16) float sm[];      // 16384 W + 512 hsm
    const int dir  = blockIdx.y;
    const int sub  = blockIdx.x;
    const int tid  = threadIdx.x;
    const int w    = tid >> 5;
    const int lane = tid & 31;
    const int gu   = sub * 8 + w;                    // global hidden unit of this warp

    const float* __restrict__ Whh = dir ? Whhb : Whhf;
    float* Wg = sm + w * 4 * HH;                     // this warp's 4 gate rows
    float* hsm = sm + 8 * 4 * HH;                    // 512 floats

    // Load 4 weight rows (i,f,g,o) for unit gu
#pragma unroll
    for (int g = 0; g < 4; g++) {
        const float4* src = (const float4*)(Whh + (long)(g * HH + gu) * HH);
        float4* dst = (float4*)(Wg + g * HH);
        for (int i = lane; i < HH / 4; i += 32) dst[i] = src[i];
    }
    float c = c0[dir * HH + gu];

    volatile int* cnt = (volatile int*)&g_cnt[dir * 32];
    __syncthreads();

    for (int t = 0; t < TT; t++) {
        // prefetch gate pre-activations (independent of h)
        float px0 = 0.f, px1 = 0.f, px2 = 0.f, px3 = 0.f;
        if (lane == 0) {
            const float* p = &g_pre[dir][t][0];
            px0 = p[gu]; px1 = p[HH + gu]; px2 = p[2 * HH + gu]; px3 = p[3 * HH + gu];
        }
        // wait until all CTAs (this dir) published step t's h
        if (tid == 0) {
            while (*cnt < NBLK * t) { }
            __threadfence();
        }
        __syncthreads();
        // stage h into SMEM
        if (tid < HH / 4)
            ((float4*)hsm)[tid] = ((const float4*)&g_h[t & 1][dir][0])[tid];
        __syncthreads();

        float a0 = 0.f, a1 = 0.f, a2 = 0.f, a3 = 0.f;
#pragma unroll
        for (int i = 0; i < HH / 32; i++) {
            int k = lane + 32 * i;
            float h = hsm[k];
            a0 += h * Wg[k];
            a1 += h * Wg[HH + k];
            a2 += h * Wg[2 * HH + k];
            a3 += h * Wg[3 * HH + k];
        }
#pragma unroll
        for (int off = 16; off; off >>= 1) {
            a0 += __shfl_down_sync(0xffffffffu, a0, off);
            a1 += __shfl_down_sync(0xffffffffu, a1, off);
            a2 += __shfl_down_sync(0xffffffffu, a2, off);
            a3 += __shfl_down_sync(0xffffffffu, a3, off);
        }
        if (lane == 0) {
            float zi = px0 + a0, zf = px1 + a1, zg = px2 + a2, zo = px3 + a3;
            float ig = 1.f / (1.f + expf(-zi));
            float fg = 1.f / (1.f + expf(-zf));
            float og = 1.f / (1.f + expf(-zo));
            c = fg * c + ig * tanhf(zg);
            float hn = og * tanhf(c);
            g_h[(t + 1) & 1][dir][gu] = hn;
            int trow = dir ? (TT - 1 - t) : t;
            g_hs[trow][dir * HH + gu] = hn;
        }
        __threadfence();
        __syncthreads();
        if (tid == 0) atomicAdd((int*)&g_cnt[dir * 32], 1);
    }
}

// ---------------------------------------------------------------------------
// Kernel 3: feats = [hs_f | hs_b] @ W_out^T + b_out   (grid = T, 256 threads)
// ---------------------------------------------------------------------------
__global__ void feats_kernel(const float* __restrict__ Wout,
                             const float* __restrict__ bout) {
    __shared__ __align__(16) float hsm[2 * HH];
    const int t = blockIdx.x;
    const int tid = threadIdx.x, w = tid >> 5, lane = tid & 31;
    ((float4*)hsm)[tid] = ((const float4*)&g_hs[t][0])[tid];
    __syncthreads();
    if (w < KK) {
        float acc = 0.f;
        const float* wr = Wout + w * 2 * HH;
        for (int k = lane; k < 2 * HH; k += 32) acc += hsm[k] * __ldg(wr + k);
#pragma unroll
        for (int off = 16; off; off >>= 1) acc += __shfl_down_sync(0xffffffffu, acc, off);
        if (lane == 0) g_feats[t][w] = acc + bout[w];
    }
}

// ---------------------------------------------------------------------------
// Kernel 4: Viterbi forward + backtrace, 1 block, 1 warp.
// Lane i (< 7) owns next-tag i; fv replicated to all lanes via shfl gather.
// ---------------------------------------------------------------------------
__global__ void viterbi_kernel(const float* __restrict__ trans,
                               float* __restrict__ out) {
    __shared__ signed char bp[TT][8];
    __shared__ signed char path_s[TT];
    const int lane = threadIdx.x;

    float tr[KK];
    if (lane < KK) {
#pragma unroll
        for (int j = 0; j < KK; j++) tr[j] = trans[lane * KK + j];
    }
    float fv = (lane == START_TAG) ? 0.f : NEGV;
    float fvv[KK];
#pragma unroll
    for (int j = 0; j < KK; j++) fvv[j] = __shfl_sync(0xffffffffu, fv, j);

    float feat = (lane < KK) ? g_feats[0][lane] : 0.f;
    for (int t = 0; t < TT; t++) {
        float fnext = (lane < KK && t + 1 < TT) ? g_feats[t + 1][lane] : 0.f;
        if (lane < KK) {
            float best = fvv[0] + tr[0];
            int bj = 0;
#pragma unroll
            for (int j = 1; j < KK; j++) {
                float v = fvv[j] + tr[j];
                if (v > best) { best = v; bj = j; }   // first-max semantics
            }
            bp[t][lane] = (signed char)bj;
            fv = best + feat;
        }
#pragma unroll
        for (int j = 0; j < KK; j++) fvv[j] = __shfl_sync(0xffffffffu, fv, j);
        feat = fnext;
    }

    if (lane == 0) {
        float best = -1e30f; int bi = 0;
#pragma unroll
        for (int i = 0; i < KK; i++) {
            float v = fvv[i] + trans[STOP_TAG * KK + i];
            if (v > best) { best = v; bi = i; }
        }
        out[0] = best;                         // path_score
        int tag = bi;
        for (int t = TT - 1; t >= 0; t--) {    // path[t]=carry; carry=bp[t][carry]
            path_s[t] = (signed char)tag;
            tag = bp[t][tag];
        }
    }
    __syncthreads();
    for (int t = lane; t < TT; t += 32) out[1 + t] = (float)path_s[t];
}

// ---------------------------------------------------------------------------
extern "C" void kernel_launch(void* const* d_in, const int* in_sizes, int n_in,
                              void* d_out, int out_size) {
    const float* embeds = (const float*)d_in[0];
    const float* h0     = (const float*)d_in[1];
    const float* c0     = (const float*)d_in[2];
    const float* Wihf   = (const float*)d_in[3];
    const float* Whhf   = (const float*)d_in[4];
    const float* bihf   = (const float*)d_in[5];
    const float* bhhf   = (const float*)d_in[6];
    const float* Wihb   = (const float*)d_in[7];
    const float* Whhb   = (const float*)d_in[8];
    const float* bihb   = (const float*)d_in[9];
    const float* bhhb   = (const float*)d_in[10];
    const float* Wout   = (const float*)d_in[11];
    const float* bout   = (const float*)d_in[12];
    const float* trans  = (const float*)d_in[13];
    float* out = (float*)d_out;

    const int lstm_smem = (8 * 4 * HH + HH) * (int)sizeof(float);  // 67584 B
    cudaFuncSetAttribute(lstm_rec, cudaFuncAttributeMaxDynamicSharedMemorySize, lstm_smem);

    init_kernel<<<1, 1024>>>(h0);
    gemm_pre<<<dim3(GATES / BN, TT / BM, 2), 256>>>(embeds, Wihf, Wihb,
                                                    bihf, bhhf, bihb, bhhb);
    lstm_rec<<<dim3(NBLK, 2), 256, lstm_smem>>>(c0, Whhf, Whhb);
    feats_kernel<<<TT, 256>>>(Wout, bout);
    viterbi_kernel<<<1, 32>>>(trans, out);
}